// round 1
// baseline (speedup 1.0000x reference)
#include <cuda_runtime.h>
#include <cuda_bf16.h>
#include <math.h>

#define NN 10000
#define EE 100000
#define E2 110000      // edges + self loops
#define HMAX 4
#define CC 200

// ---------------- scratch (device globals; no allocs allowed) ----------------
__device__ float g_bufA[NN * 800];   // layer input x
__device__ float g_bufB[NN * 800];   // layer GEMM output h
__device__ float g_asrc[NN * HMAX];
__device__ float g_adst[NN * HMAX];
__device__ float g_alpha[E2 * HMAX];
__device__ int   g_srcv[E2];
__device__ int   g_dstv[E2];
__device__ int   g_deg[NN];
__device__ int   g_off[NN + 1];
__device__ int   g_pos[NN];
__device__ int   g_eidx[E2];

// ---------------- CSR construction ----------------
__global__ void k_zero_deg() {
    int i = blockIdx.x * blockDim.x + threadIdx.x;
    if (i < NN) g_deg[i] = 0;
}

__global__ void k_build_edges(const int* __restrict__ ei) {
    int e = blockIdx.x * blockDim.x + threadIdx.x;
    if (e >= E2) return;
    int s, d;
    if (e < EE) { s = ei[e]; d = ei[EE + e]; }
    else        { s = d = e - EE; }
    g_srcv[e] = s;
    g_dstv[e] = d;
    atomicAdd(&g_deg[d], 1);
}

// one block, 1024 threads: exclusive prefix over g_deg -> g_off, g_pos
__global__ void k_scan() {
    __shared__ int ssum[1024];
    const int CH = (NN + 1023) / 1024;  // 10
    int t = threadIdx.x;
    int start = t * CH;
    int local = 0;
    for (int i = 0; i < CH; i++) {
        int idx = start + i;
        if (idx < NN) local += g_deg[idx];
    }
    ssum[t] = local;
    __syncthreads();
    for (int d = 1; d < 1024; d <<= 1) {
        int v = (t >= d) ? ssum[t - d] : 0;
        __syncthreads();
        ssum[t] += v;
        __syncthreads();
    }
    int run = (t == 0) ? 0 : ssum[t - 1];
    for (int i = 0; i < CH; i++) {
        int idx = start + i;
        if (idx < NN) {
            g_off[idx] = run;
            g_pos[idx] = run;
            run += g_deg[idx];
        }
    }
    if (t == 1023) g_off[NN] = ssum[1023];
}

__global__ void k_scatter() {
    int e = blockIdx.x * blockDim.x + threadIdx.x;
    if (e >= E2) return;
    int p = atomicAdd(&g_pos[g_dstv[e]], 1);
    g_eidx[p] = e;
}

// ---------------- fp32 SGEMM: Hout[M,Nc] = A[M,K] @ W[K,Nc] ----------------
#define BM 128
#define BN 64
#define BK 16
__global__ __launch_bounds__(256) void k_gemm(const float* __restrict__ A,
                                              const float* __restrict__ W,
                                              float* __restrict__ Hout,
                                              int M, int K, int Nc) {
    __shared__ float As[BM][BK + 1];
    __shared__ float Bs[BK][BN];
    int t  = threadIdx.x;          // 256
    int tx = t & 15;               // 0..15 -> 4 cols each
    int ty = t >> 4;               // 0..15 -> 8 rows each
    int bm = blockIdx.y * BM;
    int bn = blockIdx.x * BN;

    float c[8][4];
    #pragma unroll
    for (int i = 0; i < 8; i++)
        #pragma unroll
        for (int j = 0; j < 4; j++) c[i][j] = 0.f;

    for (int k0 = 0; k0 < K; k0 += BK) {
        // load A tile: 128x16 = 2048 elems
        #pragma unroll
        for (int l = 0; l < 8; l++) {
            int idx = t + l * 256;
            int m = idx >> 4, kk = idx & 15;
            float v = 0.f;
            if (bm + m < M && k0 + kk < K) v = A[(size_t)(bm + m) * K + k0 + kk];
            As[m][kk] = v;
        }
        // load B tile: 16x64 = 1024 elems
        #pragma unroll
        for (int l = 0; l < 4; l++) {
            int idx = t + l * 256;
            int kk = idx >> 6, n = idx & 63;
            float v = 0.f;
            if (k0 + kk < K && bn + n < Nc) v = W[(size_t)(k0 + kk) * Nc + bn + n];
            Bs[kk][n] = v;
        }
        __syncthreads();
        #pragma unroll
        for (int kk = 0; kk < BK; kk++) {
            float av[8], bv[4];
            #pragma unroll
            for (int i = 0; i < 8; i++) av[i] = As[ty * 8 + i][kk];
            #pragma unroll
            for (int j = 0; j < 4; j++) bv[j] = Bs[kk][tx * 4 + j];
            #pragma unroll
            for (int i = 0; i < 8; i++)
                #pragma unroll
                for (int j = 0; j < 4; j++) c[i][j] += av[i] * bv[j];
        }
        __syncthreads();
    }
    #pragma unroll
    for (int i = 0; i < 8; i++) {
        int row = bm + ty * 8 + i;
        if (row >= M) continue;
        #pragma unroll
        for (int j = 0; j < 4; j++) {
            int col = bn + tx * 4 + j;
            if (col < Nc) Hout[(size_t)row * Nc + col] = c[i][j];
        }
    }
}

// ---------------- attention coefficients: alpha_src/dst[n,h] ----------------
__global__ void k_alpha(const float* __restrict__ asW,
                        const float* __restrict__ adW, int H) {
    int n = blockIdx.x;
    int h = threadIdx.x >> 5;
    int lane = threadIdx.x & 31;
    if (h >= H) return;
    const float* hrow = g_bufB + (size_t)n * H * CC + h * CC;
    float s1 = 0.f, s2 = 0.f;
    for (int c = lane; c < CC; c += 32) {
        float v = hrow[c];
        s1 += v * asW[h * CC + c];
        s2 += v * adW[h * CC + c];
    }
    #pragma unroll
    for (int o = 16; o; o >>= 1) {
        s1 += __shfl_xor_sync(0xffffffffu, s1, o);
        s2 += __shfl_xor_sync(0xffffffffu, s2, o);
    }
    if (lane == 0) {
        g_asrc[n * HMAX + h] = s1;
        g_adst[n * HMAX + h] = s2;
    }
}

// ---------------- segment softmax per (dst, head), CSR gather ----------------
__global__ void k_softmax(int H, float* __restrict__ attn_out) {
    int d = blockIdx.x;
    int h = threadIdx.x >> 5;
    int lane = threadIdx.x & 31;
    if (h >= H) return;
    int beg = g_off[d], end = g_off[d + 1];
    float ad = g_adst[d * HMAX + h];

    float mx = -INFINITY;
    for (int k = beg + lane; k < end; k += 32) {
        int e = g_eidx[k];
        float v = g_asrc[g_srcv[e] * HMAX + h] + ad;
        v = v > 0.f ? v : 0.2f * v;
        mx = fmaxf(mx, v);
    }
    #pragma unroll
    for (int o = 16; o; o >>= 1) mx = fmaxf(mx, __shfl_xor_sync(0xffffffffu, mx, o));

    float sum = 0.f;
    for (int k = beg + lane; k < end; k += 32) {
        int e = g_eidx[k];
        float v = g_asrc[g_srcv[e] * HMAX + h] + ad;
        v = v > 0.f ? v : 0.2f * v;
        float ex = expf(v - mx);
        sum += ex;
        g_alpha[e * HMAX + h] = ex;
    }
    #pragma unroll
    for (int o = 16; o; o >>= 1) sum += __shfl_xor_sync(0xffffffffu, sum, o);
    float inv = 1.f / sum;

    for (int k = beg + lane; k < end; k += 32) {
        int e = g_eidx[k];
        float a = g_alpha[e * HMAX + h] * inv;
        g_alpha[e * HMAX + h] = a;
        if (attn_out) attn_out[e] = a;
    }
}

// ---------------- aggregation + bias + gelu ----------------
__device__ __forceinline__ float gelu_exact(float v) {
    return 0.5f * v * (1.0f + erff(v * 0.70710678118654752f));
}

__global__ void k_agg(const float* __restrict__ bias,
                      float* __restrict__ out, int H) {
    int d = blockIdx.x;
    int g = threadIdx.x >> 6;      // head
    int c0 = threadIdx.x & 63;
    if (g >= H) return;
    int beg = g_off[d], end = g_off[d + 1];
    int HC = H * CC;
    for (int c = c0; c < CC; c += 64) {
        float acc = 0.f;
        for (int k = beg; k < end; k++) {
            int e = g_eidx[k];
            float a = g_alpha[e * HMAX + g];
            acc += a * g_bufB[(size_t)g_srcv[e] * HC + g * CC + c];
        }
        acc += bias[g * CC + c];
        out[(size_t)d * HC + g * CC + c] = gelu_exact(acc);
    }
}

// ---------------- host launch ----------------
extern "C" void kernel_launch(void* const* d_in, const int* in_sizes, int n_in,
                              void* d_out, int out_size) {
    const float* X  = (const float*)d_in[0];
    const int*   EI = (const int*)d_in[1];
    const float *W[5], *AS[5], *AD[5], *B[5];
    int idx = 2;
    for (int i = 0; i < 5; i++) {
        W[i]  = (const float*)d_in[idx++];
        AS[i] = (const float*)d_in[idx++];
        AD[i] = (const float*)d_in[idx++];
        B[i]  = (const float*)d_in[idx++];
    }
    float* out = (float*)d_out;

    float *bufA, *bufB;
    cudaGetSymbolAddress((void**)&bufA, g_bufA);
    cudaGetSymbolAddress((void**)&bufB, g_bufB);

    // CSR build (per launch: deterministic work, graph-capturable)
    k_zero_deg<<<(NN + 255) / 256, 256>>>();
    k_build_edges<<<(E2 + 255) / 256, 256>>>(EI);
    k_scan<<<1, 1024>>>();
    k_scatter<<<(E2 + 255) / 256, 256>>>();

    const int FIN[5]  = {200, 800, 800, 800, 800};
    const int FOUT[5] = {800, 800, 800, 800, 200};
    const int HD[5]   = {4, 4, 4, 4, 1};

    const float* x = X;
    for (int i = 0; i < 5; i++) {
        int K = FIN[i], Nc = FOUT[i], H = HD[i];
        dim3 grid((Nc + BN - 1) / BN, (NN + BM - 1) / BM);
        k_gemm<<<grid, 256>>>(x, W[i], bufB, NN, K, Nc);
        k_alpha<<<NN, 32 * H>>>(AS[i], AD[i], H);
        k_softmax<<<NN, 32 * H>>>(H, (i == 4) ? (out + (size_t)NN * 200) : nullptr);
        float* o = (i == 4) ? out : bufA;
        k_agg<<<NN, 64 * H>>>(B[i], o, H);
        x = bufA;
    }
}

// round 2
// speedup vs baseline: 1.4316x; 1.4316x over previous
#include <cuda_runtime.h>
#include <cuda_bf16.h>
#include <mma.h>
#include <math.h>

using namespace nvcuda;

#define NN 10000
#define NPAD 10112          // 79 * 128
#define EE 100000
#define E2 110000
#define HMAX 4
#define CC 200
#define K0PAD 208           // 13 * 16

// ---------------- scratch (device globals; no allocs allowed) ----------------
__device__ __nv_bfloat16 g_Ahi[NPAD * 800];
__device__ __nv_bfloat16 g_Alo[NPAD * 800];
__device__ __nv_bfloat16 g_Whi[800 * 896];
__device__ __nv_bfloat16 g_Wlo[800 * 896];
__device__ float g_bufB[NPAD * 896];      // GEMM output h (padded stride)
__device__ float g_asrc[NN * HMAX];
__device__ float g_adst[NN * HMAX];
__device__ float g_alpha[E2 * HMAX];
__device__ int   g_srcv[E2];
__device__ int   g_dstv[E2];
__device__ int   g_deg[NN];
__device__ int   g_off[NN + 1];
__device__ int   g_pos[NN];
__device__ int   g_eidx[E2];

// ---------------- CSR construction ----------------
__global__ void k_zero_deg() {
    int i = blockIdx.x * blockDim.x + threadIdx.x;
    if (i < NN) g_deg[i] = 0;
}

__global__ void k_build_edges(const int* __restrict__ ei) {
    int e = blockIdx.x * blockDim.x + threadIdx.x;
    if (e >= E2) return;
    int s, d;
    if (e < EE) { s = ei[e]; d = ei[EE + e]; }
    else        { s = d = e - EE; }
    g_srcv[e] = s;
    g_dstv[e] = d;
    atomicAdd(&g_deg[d], 1);
}

__global__ void k_scan() {
    __shared__ int ssum[1024];
    const int CH = (NN + 1023) / 1024;
    int t = threadIdx.x;
    int start = t * CH;
    int local = 0;
    for (int i = 0; i < CH; i++) {
        int idx = start + i;
        if (idx < NN) local += g_deg[idx];
    }
    ssum[t] = local;
    __syncthreads();
    for (int d = 1; d < 1024; d <<= 1) {
        int v = (t >= d) ? ssum[t - d] : 0;
        __syncthreads();
        ssum[t] += v;
        __syncthreads();
    }
    int run = (t == 0) ? 0 : ssum[t - 1];
    for (int i = 0; i < CH; i++) {
        int idx = start + i;
        if (idx < NN) {
            g_off[idx] = run;
            g_pos[idx] = run;
            run += g_deg[idx];
        }
    }
    if (t == 1023) g_off[NN] = ssum[1023];
}

__global__ void k_scatter() {
    int e = blockIdx.x * blockDim.x + threadIdx.x;
    if (e >= E2) return;
    int p = atomicAdd(&g_pos[g_dstv[e]], 1);
    g_eidx[p] = e;
}

// ---------------- fp32 -> bf16 hi/lo conversions ----------------
__device__ __forceinline__ void split_bf16(float v, __nv_bfloat16& hi, __nv_bfloat16& lo) {
    hi = __float2bfloat16(v);
    lo = __float2bfloat16(v - __bfloat162float(hi));
}

// X [NN,200] -> Ahi/Alo [NPAD, K0PAD] zero-padded
__global__ void k_convert_X(const float* __restrict__ X) {
    int idx = blockIdx.x * blockDim.x + threadIdx.x;
    if (idx >= NPAD * K0PAD) return;
    int r = idx / K0PAD, c = idx % K0PAD;
    float v = (r < NN && c < 200) ? X[r * 200 + c] : 0.f;
    __nv_bfloat16 h, l;
    split_bf16(v, h, l);
    g_Ahi[idx] = h;
    g_Alo[idx] = l;
}

// W [K,Nc] -> Whi/Wlo [Kp, Np] zero-padded
__global__ void k_convert_W(const float* __restrict__ W, int K, int Nc, int Kp, int Np) {
    int idx = blockIdx.x * blockDim.x + threadIdx.x;
    if (idx >= Kp * Np) return;
    int r = idx / Np, c = idx % Np;
    float v = (r < K && c < Nc) ? W[r * Nc + c] : 0.f;
    __nv_bfloat16 h, l;
    split_bf16(v, h, l);
    g_Whi[idx] = h;
    g_Wlo[idx] = l;
}

// ---------------- split-bf16 tensor-core GEMM ----------------
// C[M,N] = (Ah+Al)[M,K] @ (Bh+Bl)[K,N], 3-term. All dims padded: M=NPAD,
// N=Cstr multiple of 128, K multiple of 16. No bounds checks.
#define SALD 24
#define SBLD 136
__global__ __launch_bounds__(256) void k_gemm_bf16(
    const __nv_bfloat16* __restrict__ Ah, const __nv_bfloat16* __restrict__ Al,
    const __nv_bfloat16* __restrict__ Bh, const __nv_bfloat16* __restrict__ Bl,
    float* __restrict__ C, int K, int Cstr, int nk)
{
    __shared__ __nv_bfloat16 sAh[128][SALD], sAl[128][SALD];
    __shared__ __nv_bfloat16 sBh[16][SBLD],  sBl[16][SBLD];

    int t = threadIdx.x;
    int w = t >> 5;
    int wm = (w >> 2) * 64;     // 0 or 64
    int wn = (w & 3) * 32;      // 0,32,64,96

    // global load mapping
    int ar = t >> 1, ac = (t & 1) * 8;       // A: 128 rows x 16 cols
    int br = t >> 4, bc = (t & 15) * 8;      // B: 16 rows x 128 cols
    const __nv_bfloat16* pAh = Ah + (size_t)(blockIdx.y * 128 + ar) * K + ac;
    const __nv_bfloat16* pAl = Al + (size_t)(blockIdx.y * 128 + ar) * K + ac;
    const __nv_bfloat16* pBh = Bh + (size_t)br * Cstr + blockIdx.x * 128 + bc;
    const __nv_bfloat16* pBl = Bl + (size_t)br * Cstr + blockIdx.x * 128 + bc;

    wmma::fragment<wmma::accumulator, 16, 16, 16, float> acc[4][2];
    #pragma unroll
    for (int i = 0; i < 4; i++)
        #pragma unroll
        for (int j = 0; j < 2; j++) wmma::fill_fragment(acc[i][j], 0.f);

    // preload tile 0
    uint4 rah = *(const uint4*)pAh;
    uint4 ral = *(const uint4*)pAl;
    uint4 rbh = *(const uint4*)pBh;
    uint4 rbl = *(const uint4*)pBl;
    *(uint4*)&sAh[ar][ac] = rah;
    *(uint4*)&sAl[ar][ac] = ral;
    *(uint4*)&sBh[br][bc] = rbh;
    *(uint4*)&sBl[br][bc] = rbl;
    __syncthreads();

    for (int kt = 0; kt < nk; kt++) {
        if (kt + 1 < nk) {
            rah = *(const uint4*)(pAh + (size_t)(kt + 1) * 16);
            ral = *(const uint4*)(pAl + (size_t)(kt + 1) * 16);
            rbh = *(const uint4*)(pBh + (size_t)(kt + 1) * 16 * Cstr);
            rbl = *(const uint4*)(pBl + (size_t)(kt + 1) * 16 * Cstr);
        }

        wmma::fragment<wmma::matrix_b, 16, 16, 16, __nv_bfloat16, wmma::row_major> fbh[2], fbl[2];
        #pragma unroll
        for (int j = 0; j < 2; j++) {
            wmma::load_matrix_sync(fbh[j], &sBh[0][wn + j * 16], SBLD);
            wmma::load_matrix_sync(fbl[j], &sBl[0][wn + j * 16], SBLD);
        }
        #pragma unroll
        for (int i = 0; i < 4; i++) {
            wmma::fragment<wmma::matrix_a, 16, 16, 16, __nv_bfloat16, wmma::row_major> fah, fal;
            wmma::load_matrix_sync(fah, &sAh[wm + i * 16][0], SALD);
            wmma::load_matrix_sync(fal, &sAl[wm + i * 16][0], SALD);
            #pragma unroll
            for (int j = 0; j < 2; j++) {
                wmma::mma_sync(acc[i][j], fah, fbh[j], acc[i][j]);
                wmma::mma_sync(acc[i][j], fah, fbl[j], acc[i][j]);
                wmma::mma_sync(acc[i][j], fal, fbh[j], acc[i][j]);
            }
        }
        __syncthreads();
        if (kt + 1 < nk) {
            *(uint4*)&sAh[ar][ac] = rah;
            *(uint4*)&sAl[ar][ac] = ral;
            *(uint4*)&sBh[br][bc] = rbh;
            *(uint4*)&sBl[br][bc] = rbl;
            __syncthreads();
        }
    }

    // epilogue: C fully padded, unconditional stores
    #pragma unroll
    for (int i = 0; i < 4; i++)
        #pragma unroll
        for (int j = 0; j < 2; j++) {
            size_t row = blockIdx.y * 128 + wm + i * 16;
            size_t col = blockIdx.x * 128 + wn + j * 16;
            wmma::store_matrix_sync(&C[row * Cstr + col], acc[i][j], Cstr, wmma::mem_row_major);
        }
}

// ---------------- attention coefficients ----------------
__global__ void k_alpha(const float* __restrict__ asW,
                        const float* __restrict__ adW, int H, int hstr) {
    int n = blockIdx.x;
    int h = threadIdx.x >> 5;
    int lane = threadIdx.x & 31;
    if (h >= H) return;
    const float* hrow = g_bufB + (size_t)n * hstr + h * CC;
    float s1 = 0.f, s2 = 0.f;
    for (int c = lane; c < CC; c += 32) {
        float v = hrow[c];
        s1 += v * asW[h * CC + c];
        s2 += v * adW[h * CC + c];
    }
    #pragma unroll
    for (int o = 16; o; o >>= 1) {
        s1 += __shfl_xor_sync(0xffffffffu, s1, o);
        s2 += __shfl_xor_sync(0xffffffffu, s2, o);
    }
    if (lane == 0) {
        g_asrc[n * HMAX + h] = s1;
        g_adst[n * HMAX + h] = s2;
    }
}

// ---------------- segment softmax ----------------
__global__ void k_softmax(int H, float* __restrict__ attn_out) {
    int d = blockIdx.x;
    int h = threadIdx.x >> 5;
    int lane = threadIdx.x & 31;
    if (h >= H) return;
    int beg = g_off[d], end = g_off[d + 1];
    float ad = g_adst[d * HMAX + h];

    float mx = -INFINITY;
    for (int k = beg + lane; k < end; k += 32) {
        int e = g_eidx[k];
        float v = g_asrc[g_srcv[e] * HMAX + h] + ad;
        v = v > 0.f ? v : 0.2f * v;
        mx = fmaxf(mx, v);
    }
    #pragma unroll
    for (int o = 16; o; o >>= 1) mx = fmaxf(mx, __shfl_xor_sync(0xffffffffu, mx, o));

    float sum = 0.f;
    for (int k = beg + lane; k < end; k += 32) {
        int e = g_eidx[k];
        float v = g_asrc[g_srcv[e] * HMAX + h] + ad;
        v = v > 0.f ? v : 0.2f * v;
        float ex = expf(v - mx);
        sum += ex;
        g_alpha[e * HMAX + h] = ex;
    }
    #pragma unroll
    for (int o = 16; o; o >>= 1) sum += __shfl_xor_sync(0xffffffffu, sum, o);
    float inv = 1.f / sum;

    for (int k = beg + lane; k < end; k += 32) {
        int e = g_eidx[k];
        float a = g_alpha[e * HMAX + h] * inv;
        g_alpha[e * HMAX + h] = a;
        if (attn_out) attn_out[e] = a;
    }
}

// ---------------- aggregation + bias + gelu (+ bf16 split for next layer) ----
__device__ __forceinline__ float gelu_exact(float v) {
    return 0.5f * v * (1.0f + erff(v * 0.70710678118654752f));
}

__global__ void k_agg(const float* __restrict__ bias, int H, int hstr,
                      __nv_bfloat16* __restrict__ outHi,
                      __nv_bfloat16* __restrict__ outLo,
                      float* __restrict__ outF) {
    int d = blockIdx.x;
    int g = threadIdx.x >> 6;
    int c0 = threadIdx.x & 63;
    if (g >= H) return;
    int beg = g_off[d], end = g_off[d + 1];
    int HC = H * CC;
    for (int c = c0; c < CC; c += 64) {
        float acc = 0.f;
        for (int k = beg; k < end; k++) {
            int e = g_eidx[k];
            float a = g_alpha[e * HMAX + g];
            acc += a * g_bufB[(size_t)g_srcv[e] * hstr + g * CC + c];
        }
        acc = gelu_exact(acc + bias[g * CC + c]);
        size_t o = (size_t)d * HC + g * CC + c;
        if (outF) {
            outF[o] = acc;
        } else {
            __nv_bfloat16 h, l;
            split_bf16(acc, h, l);
            outHi[o] = h;
            outLo[o] = l;
        }
    }
}

// ---------------- host launch ----------------
extern "C" void kernel_launch(void* const* d_in, const int* in_sizes, int n_in,
                              void* d_out, int out_size) {
    const float* X  = (const float*)d_in[0];
    const int*   EI = (const int*)d_in[1];
    const float *W[5], *AS[5], *AD[5], *B[5];
    int idx = 2;
    for (int i = 0; i < 5; i++) {
        W[i]  = (const float*)d_in[idx++];
        AS[i] = (const float*)d_in[idx++];
        AD[i] = (const float*)d_in[idx++];
        B[i]  = (const float*)d_in[idx++];
    }
    float* out = (float*)d_out;

    __nv_bfloat16 *Ahi, *Alo, *Whi, *Wlo;
    float *bufB;
    cudaGetSymbolAddress((void**)&Ahi, g_Ahi);
    cudaGetSymbolAddress((void**)&Alo, g_Alo);
    cudaGetSymbolAddress((void**)&Whi, g_Whi);
    cudaGetSymbolAddress((void**)&Wlo, g_Wlo);
    cudaGetSymbolAddress((void**)&bufB, g_bufB);

    // CSR build
    k_zero_deg<<<(NN + 255) / 256, 256>>>();
    k_build_edges<<<(E2 + 255) / 256, 256>>>(EI);
    k_scan<<<1, 1024>>>();
    k_scatter<<<(E2 + 255) / 256, 256>>>();

    // X -> bf16 hi/lo, [NPAD, K0PAD]
    k_convert_X<<<(NPAD * K0PAD + 255) / 256, 256>>>(X);

    const int KIN[5]  = {200, 800, 800, 800, 800};   // logical K
    const int KP [5]  = {K0PAD, 800, 800, 800, 800}; // padded K
    const int NC [5]  = {800, 800, 800, 800, 200};   // logical N
    const int NP [5]  = {896, 896, 896, 896, 256};   // padded N (mult of 128)
    const int HD [5]  = {4, 4, 4, 4, 1};

    for (int i = 0; i < 5; i++) {
        int Kp = KP[i], Np = NP[i], H = HD[i];
        k_convert_W<<<(Kp * Np + 255) / 256, 256>>>(W[i], KIN[i], NC[i], Kp, Np);
        dim3 grid(Np / 128, NPAD / 128);
        k_gemm_bf16<<<grid, 256>>>(Ahi, Alo, Whi, Wlo, bufB, Kp, Np, Kp / 16);
        k_alpha<<<NN, 32 * H>>>(AS[i], AD[i], H, Np);
        k_softmax<<<NN, 32 * H>>>(H, (i == 4) ? (out + (size_t)NN * 200) : nullptr);
        if (i < 4) {
            k_agg<<<NN, 64 * H>>>(B[i], H, Np, Ahi, Alo, nullptr);
        } else {
            k_agg<<<NN, 64 * H>>>(B[i], H, Np, nullptr, nullptr, out);
        }
    }
}

// round 3
// speedup vs baseline: 1.9541x; 1.3649x over previous
#include <cuda_runtime.h>
#include <cuda_bf16.h>
#include <math.h>

#define NN 10000
#define NPAD 10112          // 79 * 128
#define EE 100000
#define E2 110000
#define HMAX 4
#define CC 200
#define K0PAD 224           // 7 * 32

// ---------------- scratch (device globals; no allocs allowed) ----------------
__device__ __nv_bfloat16 g_Ahi[NPAD * 800];
__device__ __nv_bfloat16 g_Alo[NPAD * 800];
__device__ __nv_bfloat16 g_Whi[800 * 896];
__device__ __nv_bfloat16 g_Wlo[800 * 896];
__device__ float g_bufB[NPAD * 896];      // GEMM output h (padded stride)
__device__ float g_asrc[NN * HMAX];
__device__ float g_adst[NN * HMAX];
__device__ float g_alpha[E2 * HMAX];
__device__ int   g_srcv[E2];
__device__ int   g_dstv[E2];
__device__ int   g_deg[NN];
__device__ int   g_off[NN + 1];
__device__ int   g_pos[NN];
__device__ int   g_eidx[E2];

// ---------------- CSR construction ----------------
__global__ void k_zero_deg() {
    int i = blockIdx.x * blockDim.x + threadIdx.x;
    if (i < NN) g_deg[i] = 0;
}

__global__ void k_build_edges(const int* __restrict__ ei) {
    int e = blockIdx.x * blockDim.x + threadIdx.x;
    if (e >= E2) return;
    int s, d;
    if (e < EE) { s = ei[e]; d = ei[EE + e]; }
    else        { s = d = e - EE; }
    g_srcv[e] = s;
    g_dstv[e] = d;
    atomicAdd(&g_deg[d], 1);
}

__global__ void k_scan() {
    __shared__ int ssum[1024];
    const int CH = (NN + 1023) / 1024;
    int t = threadIdx.x;
    int start = t * CH;
    int local = 0;
    for (int i = 0; i < CH; i++) {
        int idx = start + i;
        if (idx < NN) local += g_deg[idx];
    }
    ssum[t] = local;
    __syncthreads();
    for (int d = 1; d < 1024; d <<= 1) {
        int v = (t >= d) ? ssum[t - d] : 0;
        __syncthreads();
        ssum[t] += v;
        __syncthreads();
    }
    int run = (t == 0) ? 0 : ssum[t - 1];
    for (int i = 0; i < CH; i++) {
        int idx = start + i;
        if (idx < NN) {
            g_off[idx] = run;
            g_pos[idx] = run;
            run += g_deg[idx];
        }
    }
    if (t == 1023) g_off[NN] = ssum[1023];
}

__global__ void k_scatter() {
    int e = blockIdx.x * blockDim.x + threadIdx.x;
    if (e >= E2) return;
    int p = atomicAdd(&g_pos[g_dstv[e]], 1);
    g_eidx[p] = e;
}

// ---------------- fp32 -> bf16 hi/lo conversions ----------------
__device__ __forceinline__ void split_bf16(float v, __nv_bfloat16& hi, __nv_bfloat16& lo) {
    hi = __float2bfloat16(v);
    lo = __float2bfloat16(v - __bfloat162float(hi));
}

__global__ void k_convert_X(const float* __restrict__ X) {
    int idx = blockIdx.x * blockDim.x + threadIdx.x;
    if (idx >= NPAD * K0PAD) return;
    int r = idx / K0PAD, c = idx % K0PAD;
    float v = (r < NN && c < 200) ? X[r * 200 + c] : 0.f;
    __nv_bfloat16 h, l;
    split_bf16(v, h, l);
    g_Ahi[idx] = h;
    g_Alo[idx] = l;
}

__global__ void k_convert_W(const float* __restrict__ W, int K, int Nc, int Kp, int Np) {
    int idx = blockIdx.x * blockDim.x + threadIdx.x;
    if (idx >= Kp * Np) return;
    int r = idx / Np, c = idx % Np;
    float v = (r < K && c < Nc) ? W[r * Nc + c] : 0.f;
    __nv_bfloat16 h, l;
    split_bf16(v, h, l);
    g_Whi[idx] = h;
    g_Wlo[idx] = l;
}

// ---------------- bf16 split-3-term mma.sync GEMM, 3-stage cp.async ---------
#define BK 32
#define STAGES 3
#define STAGE_ELEMS 16384   // bf16 elems per stage (32 KB)
#define SA_OFF 0            // A: [128][64] hi cols 0-31, lo cols 32-63 (as chunks 0-3 / 4-7)
#define SBH_OFF 8192        // Bhi: [32][128]
#define SBL_OFF 12288       // Blo: [32][128]

__device__ __forceinline__ unsigned sm_u32(const void* p) {
    return (unsigned)__cvta_generic_to_shared(p);
}

#define CP16(dst, src) \
    asm volatile("cp.async.cg.shared.global [%0], [%1], 16;" :: "r"(dst), "l"(src))
#define LDMX4(r, addr) \
    asm volatile("ldmatrix.sync.aligned.m8n8.x4.shared.b16 {%0,%1,%2,%3}, [%4];" \
        : "=r"((r)[0]), "=r"((r)[1]), "=r"((r)[2]), "=r"((r)[3]) : "r"(addr))
#define LDMX4T(r, addr) \
    asm volatile("ldmatrix.sync.aligned.m8n8.x4.trans.shared.b16 {%0,%1,%2,%3}, [%4];" \
        : "=r"((r)[0]), "=r"((r)[1]), "=r"((r)[2]), "=r"((r)[3]) : "r"(addr))
#define MMA16816(d, a, b) \
    asm volatile("mma.sync.aligned.m16n8k16.row.col.f32.bf16.bf16.f32 " \
        "{%0,%1,%2,%3}, {%4,%5,%6,%7}, {%8,%9}, {%0,%1,%2,%3};" \
        : "+f"((d)[0]), "+f"((d)[1]), "+f"((d)[2]), "+f"((d)[3]) \
        : "r"((a)[0]), "r"((a)[1]), "r"((a)[2]), "r"((a)[3]), "r"((b)[0]), "r"((b)[1]))

__global__ __launch_bounds__(256) void k_gemm_mma(
    const __nv_bfloat16* __restrict__ Ah, const __nv_bfloat16* __restrict__ Al,
    const __nv_bfloat16* __restrict__ Bh, const __nv_bfloat16* __restrict__ Bl,
    float* __restrict__ C, int K, int Cstr, int nk)
{
    extern __shared__ __nv_bfloat16 smem[];
    int t = threadIdx.x;
    int lane = t & 31;
    int w = t >> 5;
    int wm = (w >> 2) * 64;     // 0 / 64
    int wn = (w & 3) * 32;      // 0,32,64,96
    int bm = blockIdx.y * 128;
    int bn = blockIdx.x * 128;

    float acc[4][4][4];
    #pragma unroll
    for (int i = 0; i < 4; i++)
        #pragma unroll
        for (int j = 0; j < 4; j++)
            #pragma unroll
            for (int x = 0; x < 4; x++) acc[i][j][x] = 0.f;

    // per-thread cp.async source/dest precompute
    auto load_stage = [&](int kt, int s) {
        __nv_bfloat16* st = smem + s * STAGE_ELEMS;
        // A: 128 rows x 8 chunks (hi chunks 0-3, lo chunks 4-7)
        #pragma unroll
        for (int i = 0; i < 4; i++) {
            int q = t + i * 256;
            int r = q >> 3, ch = q & 7;
            const __nv_bfloat16* src = ((ch & 4) ? Al : Ah)
                + (size_t)(bm + r) * K + kt * BK + (ch & 3) * 8;
            unsigned dst = sm_u32(st + SA_OFF + r * 64 + ((ch ^ (r & 7)) << 3));
            CP16(dst, src);
        }
        // B: 32 rows x 16 chunks, hi + lo
        #pragma unroll
        for (int i = 0; i < 2; i++) {
            int q = t + i * 256;
            int kr = q >> 4, c = q & 15;
            size_t goff = (size_t)(kt * BK + kr) * Cstr + bn + c * 8;
            unsigned so = kr * 128 + ((c ^ (kr & 7)) << 3);
            CP16(sm_u32(st + SBH_OFF + so), Bh + goff);
            CP16(sm_u32(st + SBL_OFF + so), Bl + goff);
        }
    };

    #pragma unroll
    for (int s = 0; s < STAGES - 1; s++) {
        if (s < nk) load_stage(s, s);
        asm volatile("cp.async.commit_group;");
    }

    for (int kt = 0; kt < nk; kt++) {
        asm volatile("cp.async.wait_group %0;" :: "n"(STAGES - 2));
        __syncthreads();
        int nxt = kt + STAGES - 1;
        if (nxt < nk) load_stage(nxt, nxt % STAGES);
        asm volatile("cp.async.commit_group;");

        __nv_bfloat16* st = smem + (kt % STAGES) * STAGE_ELEMS;
        #pragma unroll
        for (int ks = 0; ks < 2; ks++) {
            // A fragments
            unsigned ah[4][4], al[4][4];
            int kc = ks * 2 + (lane >> 4);       // hi chunk 0..3
            #pragma unroll
            for (int mi = 0; mi < 4; mi++) {
                int r = wm + mi * 16 + (lane & 15);
                unsigned aH = sm_u32(st + SA_OFF + r * 64 + ((kc ^ (r & 7)) << 3));
                unsigned aL = sm_u32(st + SA_OFF + r * 64 + (((kc + 4) ^ (r & 7)) << 3));
                LDMX4(ah[mi], aH);
                LDMX4(al[mi], aL);
            }
            // B fragments (n16 per ldmatrix)
            unsigned bh[2][4], bl[2][4];
            int kb = ks * 16 + (lane & 15);
            #pragma unroll
            for (int nq = 0; nq < 2; nq++) {
                int n = wn + nq * 16 + (lane >> 4) * 8;
                int c = n >> 3;
                unsigned off = kb * 128 + ((c ^ (kb & 7)) << 3);
                LDMX4T(bh[nq], sm_u32(st + SBH_OFF + off));
                LDMX4T(bl[nq], sm_u32(st + SBL_OFF + off));
            }
            // MMAs: hi*hi + hi*lo + lo*hi
            #pragma unroll
            for (int mi = 0; mi < 4; mi++)
                #pragma unroll
                for (int j = 0; j < 4; j++) {
                    unsigned* ph = &bh[j >> 1][(j & 1) * 2];
                    unsigned* pl = &bl[j >> 1][(j & 1) * 2];
                    MMA16816(acc[mi][j], ah[mi], ph);
                    MMA16816(acc[mi][j], ah[mi], pl);
                    MMA16816(acc[mi][j], al[mi], ph);
                }
        }
    }

    // epilogue (all dims padded; unconditional)
    #pragma unroll
    for (int mi = 0; mi < 4; mi++)
        #pragma unroll
        for (int j = 0; j < 4; j++) {
            int row = bm + wm + mi * 16 + (lane >> 2);
            int col = bn + wn + j * 8 + (lane & 3) * 2;
            float2* p0 = (float2*)(C + (size_t)row * Cstr + col);
            float2* p1 = (float2*)(C + (size_t)(row + 8) * Cstr + col);
            *p0 = make_float2(acc[mi][j][0], acc[mi][j][1]);
            *p1 = make_float2(acc[mi][j][2], acc[mi][j][3]);
        }
}

// ---------------- attention coefficients ----------------
__global__ void k_alpha(const float* __restrict__ asW,
                        const float* __restrict__ adW, int H, int hstr) {
    int n = blockIdx.x;
    int h = threadIdx.x >> 5;
    int lane = threadIdx.x & 31;
    if (h >= H) return;
    const float* hrow = g_bufB + (size_t)n * hstr + h * CC;
    float s1 = 0.f, s2 = 0.f;
    for (int c = lane; c < CC; c += 32) {
        float v = hrow[c];
        s1 += v * asW[h * CC + c];
        s2 += v * adW[h * CC + c];
    }
    #pragma unroll
    for (int o = 16; o; o >>= 1) {
        s1 += __shfl_xor_sync(0xffffffffu, s1, o);
        s2 += __shfl_xor_sync(0xffffffffu, s2, o);
    }
    if (lane == 0) {
        g_asrc[n * HMAX + h] = s1;
        g_adst[n * HMAX + h] = s2;
    }
}

// ---------------- segment softmax ----------------
__global__ void k_softmax(int H, float* __restrict__ attn_out) {
    int d = blockIdx.x;
    int h = threadIdx.x >> 5;
    int lane = threadIdx.x & 31;
    if (h >= H) return;
    int beg = g_off[d], end = g_off[d + 1];
    float ad = g_adst[d * HMAX + h];

    float mx = -INFINITY;
    for (int k = beg + lane; k < end; k += 32) {
        int e = g_eidx[k];
        float v = g_asrc[g_srcv[e] * HMAX + h] + ad;
        v = v > 0.f ? v : 0.2f * v;
        mx = fmaxf(mx, v);
    }
    #pragma unroll
    for (int o = 16; o; o >>= 1) mx = fmaxf(mx, __shfl_xor_sync(0xffffffffu, mx, o));

    float sum = 0.f;
    for (int k = beg + lane; k < end; k += 32) {
        int e = g_eidx[k];
        float v = g_asrc[g_srcv[e] * HMAX + h] + ad;
        v = v > 0.f ? v : 0.2f * v;
        float ex = expf(v - mx);
        sum += ex;
        g_alpha[e * HMAX + h] = ex;
    }
    #pragma unroll
    for (int o = 16; o; o >>= 1) sum += __shfl_xor_sync(0xffffffffu, sum, o);
    float inv = 1.f / sum;

    for (int k = beg + lane; k < end; k += 32) {
        int e = g_eidx[k];
        float a = g_alpha[e * HMAX + h] * inv;
        g_alpha[e * HMAX + h] = a;
        if (attn_out) attn_out[e] = a;
    }
}

// ---------------- aggregation + bias + gelu (+ bf16 split for next layer) ----
__device__ __forceinline__ float gelu_exact(float v) {
    return 0.5f * v * (1.0f + erff(v * 0.70710678118654752f));
}

__global__ void k_agg(const float* __restrict__ bias, int H, int hstr,
                      __nv_bfloat16* __restrict__ outHi,
                      __nv_bfloat16* __restrict__ outLo,
                      float* __restrict__ outF) {
    int d = blockIdx.x;
    int g = threadIdx.x >> 6;
    int c0 = threadIdx.x & 63;
    if (g >= H) return;
    int beg = g_off[d], end = g_off[d + 1];
    int HC = H * CC;
    for (int c = c0; c < CC; c += 64) {
        float acc = 0.f;
        for (int k = beg; k < end; k++) {
            int e = g_eidx[k];
            float a = g_alpha[e * HMAX + g];
            acc += a * g_bufB[(size_t)g_srcv[e] * hstr + g * CC + c];
        }
        acc = gelu_exact(acc + bias[g * CC + c]);
        size_t o = (size_t)d * HC + g * CC + c;
        if (outF) {
            outF[o] = acc;
        } else {
            __nv_bfloat16 h, l;
            split_bf16(acc, h, l);
            outHi[o] = h;
            outLo[o] = l;
        }
    }
}

// ---------------- host launch ----------------
extern "C" void kernel_launch(void* const* d_in, const int* in_sizes, int n_in,
                              void* d_out, int out_size) {
    const float* X  = (const float*)d_in[0];
    const int*   EI = (const int*)d_in[1];
    const float *W[5], *AS[5], *AD[5], *B[5];
    int idx = 2;
    for (int i = 0; i < 5; i++) {
        W[i]  = (const float*)d_in[idx++];
        AS[i] = (const float*)d_in[idx++];
        AD[i] = (const float*)d_in[idx++];
        B[i]  = (const float*)d_in[idx++];
    }
    float* out = (float*)d_out;

    __nv_bfloat16 *Ahi, *Alo, *Whi, *Wlo;
    float *bufB;
    cudaGetSymbolAddress((void**)&Ahi, g_Ahi);
    cudaGetSymbolAddress((void**)&Alo, g_Alo);
    cudaGetSymbolAddress((void**)&Whi, g_Whi);
    cudaGetSymbolAddress((void**)&Wlo, g_Wlo);
    cudaGetSymbolAddress((void**)&bufB, g_bufB);

    const int SMEM_DYN = STAGES * STAGE_ELEMS * 2;   // 96 KB
    cudaFuncSetAttribute(k_gemm_mma, cudaFuncAttributeMaxDynamicSharedMemorySize, SMEM_DYN);

    const int KIN[5]  = {200, 800, 800, 800, 800};
    const int KP [5]  = {K0PAD, 800, 800, 800, 800};
    const int NC [5]  = {800, 800, 800, 800, 200};
    const int NP [5]  = {896, 896, 896, 896, 256};
    const int HD [5]  = {4, 4, 4, 4, 1};

    // ordered so launch #5 (0-based, ncu -s 5 -c 1) is the first GEMM
    k_convert_X<<<(NPAD * K0PAD + 255) / 256, 256>>>(X);
    k_convert_W<<<(KP[0] * NP[0] + 255) / 256, 256>>>(W[0], KIN[0], NC[0], KP[0], NP[0]);
    k_zero_deg<<<(NN + 255) / 256, 256>>>();
    k_build_edges<<<(E2 + 255) / 256, 256>>>(EI);
    k_scan<<<1, 1024>>>();

    for (int i = 0; i < 5; i++) {
        int Kp = KP[i], Np = NP[i], H = HD[i];
        if (i > 0)
            k_convert_W<<<(Kp * Np + 255) / 256, 256>>>(W[i], KIN[i], NC[i], Kp, Np);
        dim3 grid(Np / 128, NPAD / 128);
        k_gemm_mma<<<grid, 256, SMEM_DYN>>>(Ahi, Alo, Whi, Wlo, bufB, Kp, Np, Kp / BK);
        if (i == 0)
            k_scatter<<<(E2 + 255) / 256, 256>>>();
        k_alpha<<<NN, 32 * H>>>(AS[i], AD[i], H, Np);
        k_softmax<<<NN, 32 * H>>>(H, (i == 4) ? (out + (size_t)NN * 200) : nullptr);
        if (i < 4) {
            k_agg<<<NN, 64 * H>>>(B[i], H, Np, Ahi, Alo, nullptr);
        } else {
            k_agg<<<NN, 64 * H>>>(B[i], H, Np, nullptr, nullptr, out);
        }
    }
}